// round 1
// baseline (speedup 1.0000x reference)
#include <cuda_runtime.h>

// 8 Rot gate matrices (l*4+w), each 8 floats: u00r,u00i,u01r,u01i,u10r,u10i,u11r,u11i
__device__ float g_rot[64];

__global__ void precompute_rot_kernel(const float* __restrict__ w) {
    int g = threadIdx.x;           // 0..7, gate = layer*4 + wire; weights is (2,4,3) contiguous
    if (g < 8) {
        float phi = w[g * 3 + 0], th = w[g * 3 + 1], om = w[g * 3 + 2];
        float c = cosf(0.5f * th), s = sinf(0.5f * th);
        float a = 0.5f * (phi + om), b = 0.5f * (phi - om);
        float epr = cosf(a), epi = -sinf(a);   // exp(-i(phi+om)/2)
        float emr = cosf(b), emi = sinf(b);    // exp(+i(phi-om)/2)
        float* m = &g_rot[g * 8];
        m[0] =  epr * c; m[1] =  epi * c;      // u00 = ep*c
        m[2] = -emr * s; m[3] = -emi * s;      // u01 = -em*s
        m[4] =  emr * s; m[5] = -emi * s;      // u10 = conj(em)*s
        m[6] =  epr * c; m[7] = -epi * c;      // u11 = conj(ep)*c
    }
}

// Apply general 1q gate (gate index gi, wire) to register state.
// Wire w maps to bit position (3-w) of the 4-bit amplitude index.
#define APPLY1Q(gi, wire)                                                     \
    do {                                                                      \
        const float u00r = smat[(gi)*8+0], u00i = smat[(gi)*8+1];             \
        const float u01r = smat[(gi)*8+2], u01i = smat[(gi)*8+3];             \
        const float u10r = smat[(gi)*8+4], u10i = smat[(gi)*8+5];             \
        const float u11r = smat[(gi)*8+6], u11i = smat[(gi)*8+7];             \
        const int msk = 1 << (3 - (wire));                                    \
        _Pragma("unroll")                                                     \
        for (int i = 0; i < 16; i++)                                          \
            if (!(i & msk)) {                                                 \
                const int j = i | msk;                                        \
                float a0r = sr[i], a0i = si[i];                               \
                float a1r = sr[j], a1i = si[j];                               \
                sr[i] = u00r*a0r - u00i*a0i + u01r*a1r - u01i*a1i;            \
                si[i] = u00r*a0i + u00i*a0r + u01r*a1i + u01i*a1r;            \
                sr[j] = u10r*a0r - u10i*a0i + u11r*a1r - u11i*a1i;            \
                si[j] = u10r*a0i + u10i*a0r + u11r*a1i + u11i*a1r;            \
            }                                                                 \
    } while (0)

// CNOT(control, target): swap amplitudes with control bit set, target bit flipped.
// Pure compile-time register permutation.
#define APPLYCNOT(cw, tw)                                                     \
    do {                                                                      \
        const int mc = 1 << (3 - (cw)), mt = 1 << (3 - (tw));                 \
        _Pragma("unroll")                                                     \
        for (int i = 0; i < 16; i++)                                          \
            if ((i & mc) && !(i & mt)) {                                      \
                const int j = i | mt;                                         \
                float tr = sr[i]; sr[i] = sr[j]; sr[j] = tr;                  \
                float ti = si[i]; si[i] = si[j]; si[j] = ti;                  \
            }                                                                 \
    } while (0)

__global__ __launch_bounds__(256)
void quantum_sim_kernel(const float4* __restrict__ x, float* __restrict__ out, int M) {
    __shared__ float smat[64];
    if (threadIdx.x < 64) smat[threadIdx.x] = g_rot[threadIdx.x];
    __syncthreads();

    int m = blockIdx.x * blockDim.x + threadIdx.x;
    if (m >= M) return;

    // ---- AngleEmbedding: product state, amp(b) = P(b) * (-i)^popcount(b) ----
    float4 xv = x[m];
    float c0, s0, c1, s1, c2, s2, c3, s3;
    __sincosf(0.5f * xv.x, &s0, &c0);
    __sincosf(0.5f * xv.y, &s1, &c1);
    __sincosf(0.5f * xv.z, &s2, &c2);
    __sincosf(0.5f * xv.w, &s3, &c3);

    float sr[16], si[16];
#pragma unroll
    for (int i = 0; i < 16; i++) {
        // wire w excited <-> bit (3-w): i&8 -> wire0, i&4 -> wire1, i&2 -> wire2, i&1 -> wire3
        float p = ((i & 8) ? s0 : c0) * ((i & 4) ? s1 : c1)
                * ((i & 2) ? s2 : c2) * ((i & 1) ? s3 : c3);
        const int pc = ((i & 1) + ((i >> 1) & 1) + ((i >> 2) & 1) + ((i >> 3) & 1)) & 3;
        sr[i] = (pc == 0) ? p : ((pc == 2) ? -p : 0.0f);
        si[i] = (pc == 1) ? -p : ((pc == 3) ? p : 0.0f);
    }

    // ---- Layer 0 (r = 1) ----
    APPLY1Q(0, 0); APPLY1Q(1, 1); APPLY1Q(2, 2); APPLY1Q(3, 3);
    APPLYCNOT(0, 1); APPLYCNOT(1, 2); APPLYCNOT(2, 3); APPLYCNOT(3, 0);

    // ---- Layer 1 (r = 2) ----
    APPLY1Q(4, 0); APPLY1Q(5, 1); APPLY1Q(6, 2); APPLY1Q(7, 3);
    APPLYCNOT(0, 2); APPLYCNOT(1, 3); APPLYCNOT(2, 0); APPLYCNOT(3, 1);

    // ---- expval Z0 = sum probs(bit3=0) - sum probs(bit3=1) ----
    float e = 0.0f;
#pragma unroll
    for (int i = 0; i < 8; i++)  e += sr[i] * sr[i] + si[i] * si[i];
#pragma unroll
    for (int i = 8; i < 16; i++) e -= sr[i] * sr[i] + si[i] * si[i];

    out[m] = e;
}

extern "C" void kernel_launch(void* const* d_in, const int* in_sizes, int n_in,
                              void* d_out, int out_size) {
    const float* x = (const float*)d_in[0];        // (64, 8192, 4) fp32
    const float* weights = (const float*)d_in[1];  // (2, 4, 3) fp32
    float* out = (float*)d_out;                    // (64, 8192, 1) fp32

    int M = in_sizes[0] / 4;                       // 524288 samples

    precompute_rot_kernel<<<1, 8>>>(weights);
    quantum_sim_kernel<<<(M + 255) / 256, 256>>>((const float4*)x, out, M);
}

// round 2
// speedup vs baseline: 2.0590x; 2.0590x over previous
#include <cuda_runtime.h>

// ---------------------------------------------------------------------------
// Heisenberg-collapsed evaluation of the 4-qubit, 2-layer circuit.
//
//   <Z0> = e2x*e3x + (e0z*e1z) * (e2y*e3x + e2z)
// where each e_{w,P}(x_w) = K0 + K1*cos(x_w) + K2*sin(x_w), and the 18 K
// constants depend only on `weights` (alpha/beta/gamma from the layer-1
// wire-2 Rot folded into e2x/e2y/e2z respectively).
// ---------------------------------------------------------------------------

struct Cpx { float r, i; };
__device__ __forceinline__ Cpx cmul(Cpx a, Cpx b) { return {a.r*b.r - a.i*b.i, a.r*b.i + a.i*b.r}; }
__device__ __forceinline__ Cpx cconj(Cpx a)       { return {a.r, -a.i}; }
__device__ __forceinline__ Cpx cadd(Cpx a, Cpx b) { return {a.r + b.r, a.i + b.i}; }
__device__ __forceinline__ Cpx csub(Cpx a, Cpx b) { return {a.r - b.r, a.i - b.i}; }
__device__ __forceinline__ Cpx cmuli(Cpx a)       { return {-a.i, a.r}; }   // i*a

// Rot(phi, theta, omega) = RZ(omega) RY(theta) RZ(phi), matching reference.
// R[0]=R00, R[1]=R01, R[2]=R10, R[3]=R11.
__device__ void rot_mat(const float* __restrict__ w, Cpx R[4]) {
    float phi = w[0], th = w[1], om = w[2];
    float c = cosf(0.5f * th), s = sinf(0.5f * th);
    float a = 0.5f * (phi + om), b = 0.5f * (phi - om);
    Cpx ep = { cosf(a), -sinf(a) };   // exp(-i(phi+om)/2)
    Cpx em = { cosf(b),  sinf(b) };   // exp(+i(phi-om)/2)
    R[0] = {  ep.r * c,  ep.i * c };
    R[1] = { -em.r * s, -em.i * s };
    R[2] = {  em.r * s, -em.i * s };  // conj(em)*s
    R[3] = {  ep.r * c, -ep.i * c };  // conj(ep)*c
}

// K coefficients of <v| R^dag P R |v> for v = (cos x/2, -i sin x/2):
//   e = K0 + K1*cos(x) + K2*sin(x)
// with N = R^dag P R: K0 = (N00+N11)/2, K1 = (N00-N11)/2, K2 = Im(N01).
// P: 0 = X, 1 = Y, 2 = Z.
__device__ void exp_coeffs(const Cpx R[4], int P, float scale, float* K) {
    float N00, N11;
    Cpx N01;
    if (P == 2) {            // Z
        N00 = (R[0].r*R[0].r + R[0].i*R[0].i) - (R[2].r*R[2].r + R[2].i*R[2].i);
        N01 = csub(cmul(cconj(R[0]), R[1]), cmul(cconj(R[2]), R[3]));
        N11 = (R[1].r*R[1].r + R[1].i*R[1].i) - (R[3].r*R[3].r + R[3].i*R[3].i);
    } else if (P == 0) {     // X
        Cpx z02 = cmul(cconj(R[0]), R[2]);
        Cpx z13 = cmul(cconj(R[1]), R[3]);
        N00 = 2.0f * z02.r;
        N01 = cadd(cmul(cconj(R[0]), R[3]), cmul(cconj(R[2]), R[1]));
        N11 = 2.0f * z13.r;
    } else {                 // Y
        Cpx z02 = cmul(cconj(R[0]), R[2]);
        Cpx z13 = cmul(cconj(R[1]), R[3]);
        N00 = 2.0f * z02.i;
        // N01 = -i*conj(R00)*R11 + i*conj(R10)*R01
        Cpx t1 = cmuli(cmul(cconj(R[0]), R[3]));   //  i*conj(R00)R11
        Cpx t2 = cmuli(cmul(cconj(R[2]), R[1]));   //  i*conj(R10)R01
        N01 = csub(t2, t1);                        //  -t1 + t2
        N11 = 2.0f * z13.i;
    }
    K[0] = 0.5f * (N00 + N11) * scale;
    K[1] = 0.5f * (N00 - N11) * scale;
    K[2] = N01.i * scale;
}

__global__ __launch_bounds__(256)
void quantum_collapsed_kernel(const float4* __restrict__ x,
                              const float*  __restrict__ w,
                              float* __restrict__ out, int M) {
    // K layout: [0..2]=e0Z  [3..5]=e1Z  [6..8]=e2X*alpha
    //           [9..11]=e2Y*beta  [12..14]=e2Z*gamma  [15..17]=e3X
    __shared__ float K[18];

    int m = blockIdx.x * blockDim.x + threadIdx.x;
    // Issue the sample load first so it overlaps thread 0's constant setup.
    float4 xv = (m < M) ? x[m] : make_float4(0.f, 0.f, 0.f, 0.f);

    if (threadIdx.x == 0) {
        // alpha/beta/gamma from layer-1, wire-2 Rot: M = R^dag Z R
        Cpx R[4];
        rot_mat(w + (1 * 4 + 2) * 3, R);
        float M00 = (R[0].r*R[0].r + R[0].i*R[0].i) - (R[2].r*R[2].r + R[2].i*R[2].i);
        Cpx M01 = csub(cmul(cconj(R[0]), R[1]), cmul(cconj(R[2]), R[3]));
        float alpha = M01.r, beta = -M01.i, gamma = M00;

        Cpx R0[4], R1[4], R2[4], R3[4];
        rot_mat(w + 0 * 3, R0);   // layer 0 wire 0
        rot_mat(w + 1 * 3, R1);   // layer 0 wire 1
        rot_mat(w + 2 * 3, R2);   // layer 0 wire 2
        rot_mat(w + 3 * 3, R3);   // layer 0 wire 3
        exp_coeffs(R0, 2, 1.0f,  &K[0]);    // e0Z
        exp_coeffs(R1, 2, 1.0f,  &K[3]);    // e1Z
        exp_coeffs(R2, 0, alpha, &K[6]);    // e2X * alpha
        exp_coeffs(R2, 1, beta,  &K[9]);    // e2Y * beta
        exp_coeffs(R2, 2, gamma, &K[12]);   // e2Z * gamma
        exp_coeffs(R3, 0, 1.0f,  &K[15]);   // e3X
    }
    __syncthreads();

    if (m >= M) return;

    float c0, s0, c1, s1, c2, s2, c3, s3;
    __sincosf(xv.x, &s0, &c0);
    __sincosf(xv.y, &s1, &c1);
    __sincosf(xv.z, &s2, &c2);
    __sincosf(xv.w, &s3, &c3);

    float e0z = fmaf(K[1],  c0, fmaf(K[2],  s0, K[0]));
    float e1z = fmaf(K[4],  c1, fmaf(K[5],  s1, K[3]));
    float e2x = fmaf(K[7],  c2, fmaf(K[8],  s2, K[6]));
    float e2y = fmaf(K[10], c2, fmaf(K[11], s2, K[9]));
    float e2z = fmaf(K[13], c2, fmaf(K[14], s2, K[12]));
    float e3x = fmaf(K[16], c3, fmaf(K[17], s3, K[15]));

    float t01 = e0z * e1z;
    float r = fmaf(t01, fmaf(e2y, e3x, e2z), e2x * e3x);
    out[m] = r;
}

extern "C" void kernel_launch(void* const* d_in, const int* in_sizes, int n_in,
                              void* d_out, int out_size) {
    const float* x = (const float*)d_in[0];        // (64, 8192, 4) fp32
    const float* weights = (const float*)d_in[1];  // (2, 4, 3) fp32
    float* out = (float*)d_out;                    // (64, 8192, 1) fp32

    int M = in_sizes[0] / 4;                       // 524288 samples

    quantum_collapsed_kernel<<<(M + 255) / 256, 256>>>(
        (const float4*)x, weights, out, M);
}

// round 3
// speedup vs baseline: 3.0809x; 1.4963x over previous
#include <cuda_runtime.h>

// ---------------------------------------------------------------------------
// Heisenberg-collapsed circuit:
//   <Z0> = e2x*e3x + (e0z*e1z) * (e2y*e3x + e2z)
// e_{w,P}(x_w) = K0 + K1*cos(x_w) + K2*sin(x_w); 18 K constants from weights.
// Round 3: K setup moved to a tiny parallel kernel so the streaming kernel
// has zero serial prologue.
// ---------------------------------------------------------------------------

__device__ float g_K[18];

struct Cpx { float r, i; };
__device__ __forceinline__ Cpx cmul(Cpx a, Cpx b) { return {a.r*b.r - a.i*b.i, a.r*b.i + a.i*b.r}; }
__device__ __forceinline__ Cpx cconj(Cpx a)       { return {a.r, -a.i}; }
__device__ __forceinline__ Cpx cadd(Cpx a, Cpx b) { return {a.r + b.r, a.i + b.i}; }
__device__ __forceinline__ Cpx csub(Cpx a, Cpx b) { return {a.r - b.r, a.i - b.i}; }
__device__ __forceinline__ Cpx cmuli(Cpx a)       { return {-a.i, a.r}; }   // i*a

// Rot(phi, theta, omega) = RZ(omega) RY(theta) RZ(phi).
__device__ void rot_mat(const float* __restrict__ w, Cpx R[4]) {
    float phi = w[0], th = w[1], om = w[2];
    float c = cosf(0.5f * th), s = sinf(0.5f * th);
    float a = 0.5f * (phi + om), b = 0.5f * (phi - om);
    Cpx ep = { cosf(a), -sinf(a) };   // exp(-i(phi+om)/2)
    Cpx em = { cosf(b),  sinf(b) };   // exp(+i(phi-om)/2)
    R[0] = {  ep.r * c,  ep.i * c };
    R[1] = { -em.r * s, -em.i * s };
    R[2] = {  em.r * s, -em.i * s };  // conj(em)*s
    R[3] = {  ep.r * c, -ep.i * c };  // conj(ep)*c
}

// K coefficients of <v| R^dag P R |v> for v = (cos x/2, -i sin x/2):
// e = K0 + K1*cos(x) + K2*sin(x). P: 0=X, 1=Y, 2=Z.
__device__ void exp_coeffs(const Cpx R[4], int P, float scale, float* K) {
    float N00, N11;
    Cpx N01;
    if (P == 2) {            // Z
        N00 = (R[0].r*R[0].r + R[0].i*R[0].i) - (R[2].r*R[2].r + R[2].i*R[2].i);
        N01 = csub(cmul(cconj(R[0]), R[1]), cmul(cconj(R[2]), R[3]));
        N11 = (R[1].r*R[1].r + R[1].i*R[1].i) - (R[3].r*R[3].r + R[3].i*R[3].i);
    } else if (P == 0) {     // X
        Cpx z02 = cmul(cconj(R[0]), R[2]);
        Cpx z13 = cmul(cconj(R[1]), R[3]);
        N00 = 2.0f * z02.r;
        N01 = cadd(cmul(cconj(R[0]), R[3]), cmul(cconj(R[2]), R[1]));
        N11 = 2.0f * z13.r;
    } else {                 // Y
        Cpx z02 = cmul(cconj(R[0]), R[2]);
        Cpx z13 = cmul(cconj(R[1]), R[3]);
        N00 = 2.0f * z02.i;
        Cpx t1 = cmuli(cmul(cconj(R[0]), R[3]));   // i*conj(R00)R11
        Cpx t2 = cmuli(cmul(cconj(R[2]), R[1]));   // i*conj(R10)R01
        N01 = csub(t2, t1);
        N11 = 2.0f * z13.i;
    }
    K[0] = 0.5f * (N00 + N11) * scale;
    K[1] = 0.5f * (N00 - N11) * scale;
    K[2] = N01.i * scale;
}

// 6 threads, each produces one K triple. Threads 2-4 redundantly derive
// alpha/beta/gamma from the layer-1 wire-2 Rot (parallel, cheap).
__global__ void precompute_k(const float* __restrict__ w) {
    int t = threadIdx.x;
    if (t >= 6) return;

    // map: 0 -> (wire0, Z), 1 -> (wire1, Z), 2 -> (wire2, X*alpha),
    //      3 -> (wire2, Y*beta), 4 -> (wire2, Z*gamma), 5 -> (wire3, X)
    int wire = (t == 0) ? 0 : (t == 1) ? 1 : (t == 5) ? 3 : 2;
    int P    = (t <= 1) ? 2 : (t == 2) ? 0 : (t == 3) ? 1 : (t == 4) ? 2 : 0;

    float scale = 1.0f;
    if (t >= 2 && t <= 4) {
        Cpx R1[4];
        rot_mat(w + (1 * 4 + 2) * 3, R1);          // layer 1, wire 2
        float M00 = (R1[0].r*R1[0].r + R1[0].i*R1[0].i) - (R1[2].r*R1[2].r + R1[2].i*R1[2].i);
        Cpx M01 = csub(cmul(cconj(R1[0]), R1[1]), cmul(cconj(R1[2]), R1[3]));
        scale = (t == 2) ? M01.r : (t == 3) ? -M01.i : M00;  // alpha / beta / gamma
    }

    Cpx R[4];
    rot_mat(w + wire * 3, R);                       // layer 0
    float K[3];
    exp_coeffs(R, P, scale, K);
    g_K[t * 3 + 0] = K[0];
    g_K[t * 3 + 1] = K[1];
    g_K[t * 3 + 2] = K[2];
}

__device__ __forceinline__ float eval_sample(float4 xv, const float k[18]) {
    float c0, s0, c1, s1, c2, s2, c3, s3;
    __sincosf(xv.x, &s0, &c0);
    __sincosf(xv.y, &s1, &c1);
    __sincosf(xv.z, &s2, &c2);
    __sincosf(xv.w, &s3, &c3);
    float e0z = fmaf(k[1],  c0, fmaf(k[2],  s0, k[0]));
    float e1z = fmaf(k[4],  c1, fmaf(k[5],  s1, k[3]));
    float e2x = fmaf(k[7],  c2, fmaf(k[8],  s2, k[6]));
    float e2y = fmaf(k[10], c2, fmaf(k[11], s2, k[9]));
    float e2z = fmaf(k[13], c2, fmaf(k[14], s2, k[12]));
    float e3x = fmaf(k[16], c3, fmaf(k[17], s3, k[15]));
    return fmaf(e0z * e1z, fmaf(e2y, e3x, e2z), e2x * e3x);
}

__global__ __launch_bounds__(256)
void quantum_eval(const float4* __restrict__ x, float2* __restrict__ out, int Mpairs) {
    int t = blockIdx.x * blockDim.x + threadIdx.x;
    if (t >= Mpairs) return;

    float4 a = __ldg(&x[2 * t + 0]);
    float4 b = __ldg(&x[2 * t + 1]);

    float k[18];
#pragma unroll
    for (int i = 0; i < 18; i++) k[i] = __ldg(&g_K[i]);

    float2 r;
    r.x = eval_sample(a, k);
    r.y = eval_sample(b, k);
    out[t] = r;
}

extern "C" void kernel_launch(void* const* d_in, const int* in_sizes, int n_in,
                              void* d_out, int out_size) {
    const float* x = (const float*)d_in[0];        // (64, 8192, 4) fp32
    const float* weights = (const float*)d_in[1];  // (2, 4, 3) fp32
    float* out = (float*)d_out;                    // (64, 8192, 1) fp32

    int M = in_sizes[0] / 4;                       // 524288 samples
    int Mpairs = M / 2;                            // 262144 (M is even)

    precompute_k<<<1, 32>>>(weights);
    quantum_eval<<<(Mpairs + 255) / 256, 256>>>(
        (const float4*)x, (float2*)out, Mpairs);
}